// round 16
// baseline (speedup 1.0000x reference)
#include <cuda_runtime.h>
#include <cuda_fp16.h>
#include <mma.h>

using namespace nvcuda;

#define NBATCH 4
#define NPTS 4096
#define KNB 32
#define CH 64
#define NPOINT (NBATCH*NPTS)   // 16384
#define LDEPTH 10

#define A_LDM 40               // col-major A: [64 d-cols][32 k-rows], ldm 40 halves (mult 8)
#define B_LDM 72               // sB padded ldm (halves, mult 8)
#define C_LDM 68               // fp32 C ldm (mult 4)
#define WS_BYTES (32*C_LDM*4)  // 8704 = max(A 64*40*2=5120, C 8704)

typedef unsigned long long u64t;

// ---------------- static device scratch ----------------
__device__ int    g_idx[NPOINT*KNB];
__device__ __half g_posh[NPOINT*CH*KNB];    // [p][c][k]  fp16 pos
__device__ __half g_lp [NPOINT*CH*KNB];     // [p][c][k] pre-BN logits (fp16)
__device__ float  g_hpre [NPOINT*CH];
__device__ float  g_skpre[NPOINT*CH];
__device__ float  g_opre [NPOINT*CH];
__device__ double g_relS[3];
__device__ double g_relM[6];                // 00,01,02,11,12,22
__device__ double g_sum[4][CH];
__device__ double g_sq [4][CH];
__device__ float  g_scale[5][CH];
__device__ float  g_shift[5][CH];

__global__ void k_zero() {
    int t = threadIdx.x;
    if (t < 3) g_relS[t] = 0.0;
    if (t < 6) g_relM[t] = 0.0;
    for (int i = t; i < 4*CH; i += blockDim.x) {
        ((double*)g_sum)[i] = 0.0;
        ((double*)g_sq )[i] = 0.0;
    }
}

// ---------------- kNN: warp-per-query, per-lane uint top-10 + extraction merge ----------------
__global__ __launch_bounds__(128) void k_knn(const float* __restrict__ x) {
    __shared__ float s0[NPTS], s1[NPTS], s2[NPTS];   // 48 KB
    __shared__ int   eq_buf[4][36];
    int b = blockIdx.y;
    const float* xb = x + (size_t)b*3*NPTS;
    for (int i = threadIdx.x; i < NPTS; i += 128) {
        s0[i] = xb[i]; s1[i] = xb[NPTS+i]; s2[i] = xb[2*NPTS+i];
    }
    __syncthreads();
    int warp = threadIdx.x >> 5, lane = threadIdx.x & 31;
    int n = blockIdx.x*4 + warp;
    float qx = s0[n], qy = s1[n], qz = s2[n];
    float sqn = fmaf(qx,qx,fmaf(qy,qy,qz*qz));

    unsigned list[LDEPTH];
#pragma unroll
    for (int j = 0; j < LDEPTH; j++) list[j] = 0x7F800000u;   // +inf
#pragma unroll 2
    for (int i = 0; i < 128; i++) {
        int m = (i << 5) + lane;
        float cx = s0[m], cy = s1[m], cz = s2[m];
        float d = fmaf(cx,cx,fmaf(cy,cy,cz*cz)) + sqn
                - 2.f*fmaf(qx,cx,fmaf(qy,cy,qz*cz));
        d = fmaxf(d, 0.f);
        unsigned db = __float_as_uint(d);
#pragma unroll
        for (int j = LDEPTH-1; j >= 1; j--) list[j] = umax(list[j-1], umin(db, list[j]));
        list[0] = umin(list[0], db);
    }

    unsigned kthb = 0;
    for (int r = 0; r < 32; r++) {
        unsigned gmin = __reduce_min_sync(0xFFFFFFFFu, list[0]);
        unsigned msk  = __ballot_sync(0xFFFFFFFFu, list[0] == gmin);
        int src = __ffs(msk) - 1;
        if (lane == src) {
#pragma unroll
            for (int j = 0; j < LDEPTH-1; j++) list[j] = list[j+1];
            list[LDEPTH-1] = 0x7F800000u;
        }
        kthb = gmin;
    }

    size_t p = (size_t)b*NPTS + n;
    int* gi = g_idx + p*KNB;
    int cnt = 0, eqc = 0;
    float a0=0,a1=0,a2=0, m00=0,m01=0,m02=0,m11=0,m12=0,m22=0;
#pragma unroll 2
    for (int i = 0; i < 128; i++) {
        int m = (i << 5) + lane;
        float cx = s0[m], cy = s1[m], cz = s2[m];
        float d = fmaf(cx,cx,fmaf(cy,cy,cz*cz)) + sqn
                - 2.f*fmaf(qx,cx,fmaf(qy,cy,qz*cz));
        d = fmaxf(d, 0.f);
        unsigned db = __float_as_uint(d);
        bool lt = db < kthb;
        unsigned lm = __ballot_sync(0xFFFFFFFFu, lt);
        if (lt) {
            int off = cnt + __popc(lm & ((1u << lane) - 1u));
            if (off < KNB) {
                gi[off] = m;
                float rx = cx-qx, ry = cy-qy, rz = cz-qz;
                a0 += rx; a1 += ry; a2 += rz;
                m00 += rx*rx; m01 += rx*ry; m02 += rx*rz;
                m11 += ry*ry; m12 += ry*rz; m22 += rz*rz;
            }
        }
        cnt += __popc(lm);
        bool eqp = (db == kthb);
        unsigned em = __ballot_sync(0xFFFFFFFFu, eqp);
        if (em) {
            if (eqp) {
                int off = eqc + __popc(em & ((1u << lane) - 1u));
                if (off < 34) eq_buf[warp][off] = m;
            }
            eqc += __popc(em);
        }
    }
    int cntc = cnt < KNB ? cnt : KNB;
    int need = KNB - cntc;
    __syncwarp();
    if (lane < need && lane < eqc && lane < 34) {
        int id = eq_buf[warp][lane];
        gi[cntc + lane] = id;
        float rx = s0[id]-qx, ry = s1[id]-qy, rz = s2[id]-qz;
        a0 += rx; a1 += ry; a2 += rz;
        m00 += rx*rx; m01 += rx*ry; m02 += rx*rz;
        m11 += ry*ry; m12 += ry*rz; m22 += rz*rz;
    }
#pragma unroll
    for (int off = 16; off > 0; off >>= 1) {
        a0  += __shfl_down_sync(~0u,a0 ,off); a1  += __shfl_down_sync(~0u,a1 ,off);
        a2  += __shfl_down_sync(~0u,a2 ,off); m00 += __shfl_down_sync(~0u,m00,off);
        m01 += __shfl_down_sync(~0u,m01,off); m02 += __shfl_down_sync(~0u,m02,off);
        m11 += __shfl_down_sync(~0u,m11,off); m12 += __shfl_down_sync(~0u,m12,off);
        m22 += __shfl_down_sync(~0u,m22,off);
    }
    if (lane == 0) {
        atomicAdd(&g_relS[0],(double)a0); atomicAdd(&g_relS[1],(double)a1);
        atomicAdd(&g_relS[2],(double)a2);
        atomicAdd(&g_relM[0],(double)m00); atomicAdd(&g_relM[1],(double)m01);
        atomicAdd(&g_relM[2],(double)m02); atomicAdd(&g_relM[3],(double)m11);
        atomicAdd(&g_relM[4],(double)m12); atomicAdd(&g_relM[5],(double)m22);
    }
}

__global__ void k_bn1fin(const float* __restrict__ Wp1,
                         const float* __restrict__ gw, const float* __restrict__ bw) {
    int c = threadIdx.x;
    double w0 = Wp1[c*3], w1 = Wp1[c*3+1], w2 = Wp1[c*3+2];
    double NT = (double)NPOINT * KNB;
    double mean = (g_relS[0]*w0 + g_relS[1]*w1 + g_relS[2]*w2) / NT;
    double E2 = (w0*w0*g_relM[0] + w1*w1*g_relM[3] + w2*w2*g_relM[5]
               + 2.0*(w0*w1*g_relM[1] + w0*w2*g_relM[2] + w1*w2*g_relM[4])) / NT;
    double var = E2 - mean*mean; if (var < 0) var = 0;
    float sc = (float)((double)gw[c] * rsqrt(var + 1e-5));
    g_scale[0][c] = sc;
    g_shift[0][c] = (float)((double)bw[c] - mean*sc);
}

// ---------------- GEMV1 via wmma: pos = relu(bn(rel@Wp1)) @ Wp2 ----------------
// warp-per-point; A staged col-major [d][k] (conflict-free stores); B padded ldm.
__global__ __launch_bounds__(128, 3) void k_mlp1(const float* __restrict__ x,
        const float* __restrict__ Wp1, const float* __restrict__ Wp2) {
    __shared__ __half sB[CH*B_LDM];                    // B[d][c] at d*72+c, 9 KB
    __shared__ float sA0[CH],sA1[CH],sA2[CH],sSc[CH],sSh[CH];
    __shared__ __align__(32) unsigned char ws[4][WS_BYTES];  // per-warp A/C union
    int tid = threadIdx.x;
    for (int i = tid; i < CH; i += 128) {
        sA0[i]=Wp1[i*3]; sA1[i]=Wp1[i*3+1]; sA2[i]=Wp1[i*3+2];
        sSc[i]=g_scale[0][i]; sSh[i]=g_shift[0][i];
    }
    for (int i = tid; i < CH*CH; i += 128) {
        int d = i >> 6, c = i & 63;
        sB[d*B_LDM + c] = __float2half_rn(Wp2[c*CH + d]);
    }
    __syncthreads();
    int warp = tid >> 5, lane = tid & 31;
    size_t p = (size_t)blockIdx.x*4 + warp;
    const float* xb = x + (size_t)(p >> 12)*3*NPTS;
    int n = (int)(p & 4095);
    int id = g_idx[p*KNB + lane];
    float rx = xb[id]-xb[n], ry = xb[NPTS+id]-xb[NPTS+n], rz = xb[2*NPTS+id]-xb[2*NPTS+n];

    // stage A col-major: element (k=lane, d) at A[d*A_LDM + lane]
    __half* A = (__half*)ws[warp];
#pragma unroll 4
    for (int d = 0; d < CH; d++) {
        float v = fmaf(rx, sA0[d], fmaf(ry, sA1[d], rz*sA2[d]));
        float u = fmaxf(fmaf(sSc[d], v, sSh[d]), 0.f);
        A[d*A_LDM + lane] = __float2half_rn(u);
    }
    __syncwarp();

    wmma::fragment<wmma::accumulator, 16,16,16, float> Cf[2][4];
#pragma unroll
    for (int m = 0; m < 2; m++)
#pragma unroll
        for (int nn = 0; nn < 4; nn++) wmma::fill_fragment(Cf[m][nn], 0.f);
#pragma unroll
    for (int ks = 0; ks < 4; ks++) {
        wmma::fragment<wmma::matrix_b, 16,16,16, __half, wmma::row_major> Bf[4];
#pragma unroll
        for (int nn = 0; nn < 4; nn++)
            wmma::load_matrix_sync(Bf[nn], sB + ks*16*B_LDM + nn*16, B_LDM);
#pragma unroll
        for (int m = 0; m < 2; m++) {
            wmma::fragment<wmma::matrix_a, 16,16,16, __half, wmma::col_major> Af;
            wmma::load_matrix_sync(Af, A + m*16 + ks*16*A_LDM, A_LDM);
#pragma unroll
            for (int nn = 0; nn < 4; nn++)
                wmma::mma_sync(Cf[m][nn], Af, Bf[nn], Cf[m][nn]);
        }
    }
    __syncwarp();
    float* Cs = (float*)ws[warp];
#pragma unroll
    for (int m = 0; m < 2; m++)
#pragma unroll
        for (int nn = 0; nn < 4; nn++)
            wmma::store_matrix_sync(Cs + m*16*C_LDM + nn*16, Cf[m][nn], C_LDM, wmma::mem_row_major);
    __syncwarp();
    __half* out = g_posh + p*(CH*KNB);
    const float4* crow = (const float4*)&Cs[lane*C_LDM];   // 272B rows: LDS.128 conflict-free
#pragma unroll
    for (int i = 0; i < 16; i++) {
        float4 v = crow[i];
        out[(4*i+0)*KNB + lane] = __float2half_rn(v.x);
        out[(4*i+1)*KNB + lane] = __float2half_rn(v.y);
        out[(4*i+2)*KNB + lane] = __float2half_rn(v.z);
        out[(4*i+3)*KNB + lane] = __float2half_rn(v.w);
    }
}

// ---------------- GEMV2 via wmma: lp = (q - kf + pos) @ Wa ----------------
__global__ __launch_bounds__(128, 3) void k_mlp2(const float* __restrict__ x,
        const float* __restrict__ Wq, const float* __restrict__ Wkv,
        const float* __restrict__ Wa) {
    __shared__ __half sB[CH*B_LDM];
    __shared__ float sQ0[CH],sQ1[CH],sQ2[CH],sK0[CH],sK1[CH],sK2[CH];
    __shared__ __align__(32) unsigned char ws[4][WS_BYTES];
    int tid = threadIdx.x;
    for (int i = tid; i < CH; i += 128) {
        sQ0[i]=Wq [i*3]; sQ1[i]=Wq [i*3+1]; sQ2[i]=Wq [i*3+2];
        sK0[i]=Wkv[i*3]; sK1[i]=Wkv[i*3+1]; sK2[i]=Wkv[i*3+2];
    }
    for (int i = tid; i < CH*CH; i += 128) {
        int d = i >> 6, c = i & 63;
        sB[d*B_LDM + c] = __float2half_rn(Wa[c*CH + d]);
    }
    __syncthreads();
    int warp = tid >> 5, lane = tid & 31;
    size_t p = (size_t)blockIdx.x*4 + warp;
    const float* xb = x + (size_t)(p >> 12)*3*NPTS;
    int n = (int)(p & 4095);
    float qx = xb[n], qy = xb[NPTS+n], qz = xb[2*NPTS+n];
    int id = g_idx[p*KNB + lane];
    float rx = xb[id]-qx, ry = xb[NPTS+id]-qy, rz = xb[2*NPTS+id]-qz;
    const __half* po = g_posh + p*(CH*KNB) + lane;

    __half* A = (__half*)ws[warp];
#pragma unroll 4
    for (int d = 0; d < CH; d++) {
        float pv = __half2float(po[d*KNB]);
        float t = fmaf(qx,sQ0[d],fmaf(qy,sQ1[d],qz*sQ2[d]))
                - fmaf(rx,sK0[d],fmaf(ry,sK1[d],rz*sK2[d])) + pv;
        A[d*A_LDM + lane] = __float2half_rn(t);
    }
    __syncwarp();

    wmma::fragment<wmma::accumulator, 16,16,16, float> Cf[2][4];
#pragma unroll
    for (int m = 0; m < 2; m++)
#pragma unroll
        for (int nn = 0; nn < 4; nn++) wmma::fill_fragment(Cf[m][nn], 0.f);
#pragma unroll
    for (int ks = 0; ks < 4; ks++) {
        wmma::fragment<wmma::matrix_b, 16,16,16, __half, wmma::row_major> Bf[4];
#pragma unroll
        for (int nn = 0; nn < 4; nn++)
            wmma::load_matrix_sync(Bf[nn], sB + ks*16*B_LDM + nn*16, B_LDM);
#pragma unroll
        for (int m = 0; m < 2; m++) {
            wmma::fragment<wmma::matrix_a, 16,16,16, __half, wmma::col_major> Af;
            wmma::load_matrix_sync(Af, A + m*16 + ks*16*A_LDM, A_LDM);
#pragma unroll
            for (int nn = 0; nn < 4; nn++)
                wmma::mma_sync(Cf[m][nn], Af, Bf[nn], Cf[m][nn]);
        }
    }
    __syncwarp();
    float* Cs = (float*)ws[warp];
#pragma unroll
    for (int m = 0; m < 2; m++)
#pragma unroll
        for (int nn = 0; nn < 4; nn++)
            wmma::store_matrix_sync(Cs + m*16*C_LDM + nn*16, Cf[m][nn], C_LDM, wmma::mem_row_major);
    __syncwarp();
    __half* out = g_lp + p*(CH*KNB);
    const float4* crow = (const float4*)&Cs[lane*C_LDM];
#pragma unroll
    for (int i = 0; i < 16; i++) {
        float4 v = crow[i];
        out[(4*i+0)*KNB + lane] = __float2half_rn(v.x);
        out[(4*i+1)*KNB + lane] = __float2half_rn(v.y);
        out[(4*i+2)*KNB + lane] = __float2half_rn(v.z);
        out[(4*i+3)*KNB + lane] = __float2half_rn(v.w);
    }
}

// ---------------- lp (fp16) channel stats reduce -> stat0 ----------------
__global__ __launch_bounds__(256) void k_reduce_lp() {
    const __half2* src = (const __half2*)g_lp;
    __shared__ float s1[CH], s2[CH];
    if (threadIdx.x < CH) { s1[threadIdx.x] = 0.f; s2[threadIdx.x] = 0.f; }
    __syncthreads();
    int t = blockIdx.x*blockDim.x + threadIdx.x;
    int stride = gridDim.x*blockDim.x;
    int c = (t >> 4) & 63;
    float a = 0.f, q = 0.f;
    int total = NPOINT*CH*KNB/2;
    for (int j = t; j < total; j += stride) {
        float2 f = __half22float2(src[j]);
        a += f.x + f.y;
        q += f.x*f.x + f.y*f.y;
    }
    atomicAdd(&s1[c], a); atomicAdd(&s2[c], q);
    __syncthreads();
    if (threadIdx.x < CH) {
        atomicAdd(&g_sum[0][threadIdx.x], (double)s1[threadIdx.x]);
        atomicAdd(&g_sq [0][threadIdx.x], (double)s2[threadIdx.x]);
    }
}

// ---------------- per-channel sum/sumsq reduce (float sources) ----------------
__global__ __launch_bounds__(256) void k_reduce(int sel, int nElem, int shift, int statIdx) {
    const float* src = sel==1 ? g_hpre : sel==2 ? g_skpre : g_opre;
    __shared__ float s1[CH], s2[CH];
    if (threadIdx.x < CH) { s1[threadIdx.x] = 0.f; s2[threadIdx.x] = 0.f; }
    __syncthreads();
    int t = blockIdx.x*blockDim.x + threadIdx.x;
    int stride = gridDim.x*blockDim.x;
    int c = (t >> shift) & 63;
    float a = 0.f, q = 0.f;
    for (int i = t; i < nElem; i += stride) { float v = src[i]; a += v; q += v*v; }
    atomicAdd(&s1[c], a); atomicAdd(&s2[c], q);
    __syncthreads();
    if (threadIdx.x < CH) {
        atomicAdd(&g_sum[statIdx][threadIdx.x], (double)s1[threadIdx.x]);
        atomicAdd(&g_sq [statIdx][threadIdx.x], (double)s2[threadIdx.x]);
    }
}

__global__ __launch_bounds__(256) void k_reduce_hs(int blocksPer) {
    int which = blockIdx.x >= blocksPer;
    const float* src = which ? g_skpre : g_hpre;
    int statIdx = which ? 2 : 1;
    int bid = which ? blockIdx.x - blocksPer : blockIdx.x;
    __shared__ float s1[CH], s2[CH];
    if (threadIdx.x < CH) { s1[threadIdx.x] = 0.f; s2[threadIdx.x] = 0.f; }
    __syncthreads();
    int t = bid*blockDim.x + threadIdx.x;
    int stride = blocksPer*blockDim.x;
    int c = t & 63;
    float a = 0.f, q = 0.f;
    for (int i = t; i < NPOINT*CH; i += stride) { float v = src[i]; a += v; q += v*v; }
    atomicAdd(&s1[c], a); atomicAdd(&s2[c], q);
    __syncthreads();
    if (threadIdx.x < CH) {
        atomicAdd(&g_sum[statIdx][threadIdx.x], (double)s1[threadIdx.x]);
        atomicAdd(&g_sq [statIdx][threadIdx.x], (double)s2[threadIdx.x]);
    }
}

__global__ void k_bnfin(int statIdx, int bnIdx, float cnt,
                        const float* __restrict__ gw, const float* __restrict__ bw) {
    int c = threadIdx.x;
    double mean = g_sum[statIdx][c] / (double)cnt;
    double var  = g_sq [statIdx][c] / (double)cnt - mean*mean;
    if (var < 0) var = 0;
    float sc = (float)((double)gw[c] * rsqrt(var + 1e-5));
    g_scale[bnIdx][c] = sc;
    g_shift[bnIdx][c] = (float)((double)bw[c] - mean*sc);
}

__global__ void k_bnfin2(const float* __restrict__ gc, const float* __restrict__ bc,
                         const float* __restrict__ gs, const float* __restrict__ bs) {
    int c = threadIdx.x & 63;
    int which = threadIdx.x >> 6;
    int statIdx = which ? 2 : 1;
    int bnIdx   = which ? 3 : 2;
    const float* gw = which ? gs : gc;
    const float* bw = which ? bs : bc;
    double mean = g_sum[statIdx][c] / (double)NPOINT;
    double var  = g_sq [statIdx][c] / (double)NPOINT - mean*mean;
    if (var < 0) var = 0;
    float sc = (float)((double)gw[c] * rsqrt(var + 1e-5));
    g_scale[bnIdx][c] = sc;
    g_shift[bnIdx][c] = (float)((double)bw[c] - mean*sc);
}

// ---------------- attention + aggregation + h/sk pre ----------------
__global__ __launch_bounds__(128) void k_attn(const float* __restrict__ x,
        const float* __restrict__ Wkv, const float* __restrict__ Wc1,
        const float* __restrict__ Wsk) {
    __shared__ float sV0[CH], sV1[CH], sV2[CH];
    __shared__ float sC1T[CH*CH];   // [d][c]
    __shared__ float sSkT[6*CH];    // [j][c]
    __shared__ float rels[4][3][KNB];
    __shared__ float aggs[4][CH];
    int tid = threadIdx.x;
    for (int i = tid; i < CH; i += 128) {
        sV0[i]=Wkv[(CH+i)*3]; sV1[i]=Wkv[(CH+i)*3+1]; sV2[i]=Wkv[(CH+i)*3+2];
    }
    for (int i = tid; i < CH*CH; i += 128) {
        int d = i >> 6, c = i & 63;
        sC1T[i] = Wc1[c*CH + d];
    }
    for (int i = tid; i < 6*CH; i += 128) {
        int j = i >> 6, c = i & 63;
        sSkT[i] = Wsk[c*6 + j];
    }
    __syncthreads();
    int warp = tid >> 5, lane = tid & 31;
    size_t p = (size_t)blockIdx.x*4 + warp;
    int b = (int)(p >> 12), n = (int)(p & 4095);
    const float* xb = x + (size_t)b*3*NPTS;
    float qx = xb[n], qy = xb[NPTS+n], qz = xb[2*NPTS+n];
    int id = g_idx[p*KNB + lane];
    float cx = xb[id], cy = xb[NPTS+id], cz = xb[2*NPTS+id];
    rels[warp][0][lane] = cx-qx; rels[warp][1][lane] = cy-qy; rels[warp][2][lane] = cz-qz;
    float mx = cx, my = cy, mz = cz;
#pragma unroll
    for (int off = 16; off > 0; off >>= 1) {
        mx = fmaxf(mx, __shfl_xor_sync(~0u, mx, off));
        my = fmaxf(my, __shfl_xor_sync(~0u, my, off));
        mz = fmaxf(mz, __shfl_xor_sync(~0u, mz, off));
    }
    __syncwarp();
#pragma unroll
    for (int half = 0; half < 2; half++) {
        int c = lane + 32*half;
        float lg[KNB], pv[KNB];
        const __half2* lp2 = (const __half2*)(g_lp   + p*(CH*KNB) + (size_t)c*KNB);
        const __half2* po2 = (const __half2*)(g_posh + p*(CH*KNB) + (size_t)c*KNB);
#pragma unroll
        for (int i = 0; i < KNB/2; i++) {
            float2 f = __half22float2(lp2[i]);
            lg[2*i] = f.x; lg[2*i+1] = f.y;
        }
#pragma unroll
        for (int i = 0; i < KNB/2; i++) {
            float2 w = __half22float2(po2[i]);
            pv[2*i] = w.x; pv[2*i+1] = w.y;
        }
        float scl = g_scale[1][c], shf = g_shift[1][c];
        float m = 0.f;
#pragma unroll
        for (int j = 0; j < KNB; j++) { lg[j] = fmaxf(scl*lg[j]+shf, 0.f); m = fmaxf(m, lg[j]); }
        float s = 0.f;
#pragma unroll
        for (int j = 0; j < KNB; j++) { lg[j] = __expf(lg[j]-m); s += lg[j]; }
        float r = 1.f/s;
        float w0 = sV0[c], w1 = sV1[c], w2 = sV2[c];
        float a = 0.f;
#pragma unroll
        for (int j = 0; j < KNB; j++) {
            float vf = rels[warp][0][j]*w0 + rels[warp][1][j]*w1 + rels[warp][2][j]*w2;
            a += lg[j]*(vf + pv[j]);
        }
        aggs[warp][c] = a*r;
    }
    __syncwarp();
#pragma unroll
    for (int half = 0; half < 2; half++) {
        int c = lane + 32*half;
        float acc = 0.f;
#pragma unroll 8
        for (int d = 0; d < CH; d++) acc += aggs[warp][d]*sC1T[d*CH + c];
        g_hpre[p*CH + c] = acc;
        g_skpre[p*CH + c] = qx*sSkT[0*CH+c] + qy*sSkT[1*CH+c] + qz*sSkT[2*CH+c]
                          + mx*sSkT[3*CH+c] + my*sSkT[4*CH+c] + mz*sSkT[5*CH+c];
    }
}

// ---------------- gate GEMV 128->64 ----------------
__global__ __launch_bounds__(128) void k_out1(const float* __restrict__ Wga) {
    __shared__ float sWT[128*CH];
    __shared__ float hs[4][128];
    int tid = threadIdx.x;
    for (int idx = tid; idx < CH*128; idx += 128) {
        int i = idx >> 6, c = idx & 63;
        sWT[idx] = Wga[c*128 + i];
    }
    __syncthreads();
    int warp = tid >> 5, lane = tid & 31;
    size_t p = (size_t)blockIdx.x*4 + warp;
#pragma unroll
    for (int half = 0; half < 2; half++) {
        int c = lane + 32*half;
        hs[warp][c]     = fmaxf(g_scale[2][c]*g_hpre [p*CH+c] + g_shift[2][c], 0.f);
        hs[warp][64+c]  = fmaxf(g_scale[3][c]*g_skpre[p*CH+c] + g_shift[3][c], 0.f);
    }
    __syncwarp();
#pragma unroll
    for (int half = 0; half < 2; half++) {
        int c = lane + 32*half;
        float acc = 0.f;
#pragma unroll 8
        for (int i = 0; i < 128; i++) acc += hs[warp][i] * sWT[i*CH + c];
        g_opre[p*CH + c] = acc;
    }
}

// ---------------- final BN + transpose ----------------
__global__ __launch_bounds__(256) void k_out2(float* __restrict__ out) {
    int total = NPOINT*CH;
    for (int o = blockIdx.x*blockDim.x + threadIdx.x; o < total; o += gridDim.x*blockDim.x) {
        int n  = o & 4095;
        int bc = o >> 12;
        int c  = bc & 63;
        int b  = bc >> 6;
        float v = g_opre[(((size_t)b<<12) + n)*CH + c];
        out[o] = fmaxf(g_scale[4][c]*v + g_shift[4][c], 0.f);
    }
}

extern "C" void kernel_launch(void* const* d_in, const int* in_sizes, int n_in,
                              void* d_out, int out_size) {
    const float* x   = (const float*)d_in[0];
    const float* Wq  = (const float*)d_in[1];
    const float* Wkv = (const float*)d_in[2];
    const float* Wp1 = (const float*)d_in[3];
    const float* Wp2 = (const float*)d_in[4];
    const float* Wa  = (const float*)d_in[5];
    const float* Wc1 = (const float*)d_in[6];
    const float* Wsk = (const float*)d_in[7];
    const float* Wga = (const float*)d_in[8];
    const float* g_p = (const float*)d_in[9],  *b_p = (const float*)d_in[10];
    const float* g_a = (const float*)d_in[11], *b_a = (const float*)d_in[12];
    const float* g_c = (const float*)d_in[13], *b_c = (const float*)d_in[14];
    const float* g_sk= (const float*)d_in[15], *b_sk= (const float*)d_in[16];
    const float* g_ga= (const float*)d_in[17], *b_ga= (const float*)d_in[18];
    float* out = (float*)d_out;

    k_zero<<<1,256>>>();
    k_knn<<<dim3(NPTS/4, NBATCH), 128>>>(x);
    k_bn1fin<<<1,64>>>(Wp1, g_p, b_p);
    k_mlp1<<<NPOINT/4, 128>>>(x, Wp1, Wp2);
    k_mlp2<<<NPOINT/4, 128>>>(x, Wq, Wkv, Wa);
    k_reduce_lp<<<512,256>>>();
    k_bnfin<<<1,64>>>(0, 1, (float)(NPOINT*KNB), g_a, b_a);
    k_attn<<<NPOINT/4, 128>>>(x, Wkv, Wc1, Wsk);
    k_reduce_hs<<<512,256>>>(256);
    k_bnfin2<<<1,128>>>(g_c, b_c, g_sk, b_sk);
    k_out1<<<NPOINT/4, 128>>>(Wga);
    k_reduce<<<256,256>>>(3, NPOINT*CH, 0, 3);
    k_bnfin<<<1,64>>>(3, 4, (float)NPOINT, g_ga, b_ga);
    k_out2<<<512,256>>>(out);
}

// round 17
// speedup vs baseline: 1.0344x; 1.0344x over previous
#include <cuda_runtime.h>
#include <cuda_fp16.h>

#define NBATCH 4
#define NPTS 4096
#define KNB 32
#define CH 64
#define NPOINT (NBATCH*NPTS)   // 16384
#define LDEPTH 8

typedef unsigned long long u64t;

__device__ __forceinline__ u64t pack2(float lo, float hi) {
    u64t r; asm("mov.b64 %0, {%1,%2};" : "=l"(r) : "f"(lo), "f"(hi)); return r;
}
__device__ __forceinline__ void unpack2(u64t v, float& lo, float& hi) {
    asm("mov.b64 {%0,%1}, %2;" : "=f"(lo), "=f"(hi) : "l"(v));
}
__device__ __forceinline__ u64t fma2(u64t a, u64t b, u64t c) {
    u64t d; asm("fma.rn.f32x2 %0, %1, %2, %3;" : "=l"(d) : "l"(a), "l"(b), "l"(c)); return d;
}

// ---------------- static device scratch ----------------
__device__ int    g_idx[NPOINT*KNB];
__device__ __half g_posh[NPOINT*CH*KNB];    // [p][c][k]  fp16 pos
__device__ __half g_lp [NPOINT*CH*KNB];     // [p][c][k] pre-BN logits (fp16)
__device__ float  g_hpre [NPOINT*CH];
__device__ float  g_skpre[NPOINT*CH];
__device__ float  g_opre [NPOINT*CH];
__device__ double g_relS[3];
__device__ double g_relM[6];                // 00,01,02,11,12,22
__device__ double g_sum[4][CH];
__device__ double g_sq [4][CH];
__device__ float  g_scale[5][CH];
__device__ float  g_shift[5][CH];

__global__ void k_zero() {
    int t = threadIdx.x;
    if (t < 3) g_relS[t] = 0.0;
    if (t < 6) g_relM[t] = 0.0;
    for (int i = t; i < 4*CH; i += blockDim.x) {
        ((double*)g_sum)[i] = 0.0;
        ((double*)g_sq )[i] = 0.0;
    }
}

// ---------------- kNN: warp-per-query, per-lane uint top-8 + extraction merge ----------------
__global__ __launch_bounds__(128) void k_knn(const float* __restrict__ x) {
    __shared__ float s0[NPTS], s1[NPTS], s2[NPTS];   // 48 KB
    __shared__ int   eq_buf[4][36];
    int b = blockIdx.y;
    const float* xb = x + (size_t)b*3*NPTS;
    for (int i = threadIdx.x; i < NPTS; i += 128) {
        s0[i] = xb[i]; s1[i] = xb[NPTS+i]; s2[i] = xb[2*NPTS+i];
    }
    __syncthreads();
    int warp = threadIdx.x >> 5, lane = threadIdx.x & 31;
    int n = blockIdx.x*4 + warp;
    float qx = s0[n], qy = s1[n], qz = s2[n];
    float sqn = fmaf(qx,qx,fmaf(qy,qy,qz*qz));

    unsigned list[LDEPTH];
#pragma unroll
    for (int j = 0; j < LDEPTH; j++) list[j] = 0x7F800000u;   // +inf
#pragma unroll 2
    for (int i = 0; i < 128; i++) {
        int m = (i << 5) + lane;
        float cx = s0[m], cy = s1[m], cz = s2[m];
        float d = fmaf(cx,cx,fmaf(cy,cy,cz*cz)) + sqn
                - 2.f*fmaf(qx,cx,fmaf(qy,cy,qz*cz));
        d = fmaxf(d, 0.f);
        unsigned db = __float_as_uint(d);
#pragma unroll
        for (int j = LDEPTH-1; j >= 1; j--) list[j] = umax(list[j-1], umin(db, list[j]));
        list[0] = umin(list[0], db);
    }

    // extraction tournament: 32 rounds -> 32nd smallest of union (w.h.p. exact)
    unsigned kthb = 0;
    for (int r = 0; r < 32; r++) {
        unsigned gmin = __reduce_min_sync(0xFFFFFFFFu, list[0]);
        unsigned msk  = __ballot_sync(0xFFFFFFFFu, list[0] == gmin);
        int src = __ffs(msk) - 1;
        if (lane == src) {
#pragma unroll
            for (int j = 0; j < LDEPTH-1; j++) list[j] = list[j+1];
            list[LDEPTH-1] = 0x7F800000u;
        }
        kthb = gmin;
    }

    // rescan: strict-less indices (ascending), equals buffer, rel moments
    size_t p = (size_t)b*NPTS + n;
    int* gi = g_idx + p*KNB;
    int cnt = 0, eqc = 0;
    float a0=0,a1=0,a2=0, m00=0,m01=0,m02=0,m11=0,m12=0,m22=0;
#pragma unroll 2
    for (int i = 0; i < 128; i++) {
        int m = (i << 5) + lane;
        float cx = s0[m], cy = s1[m], cz = s2[m];
        float d = fmaf(cx,cx,fmaf(cy,cy,cz*cz)) + sqn
                - 2.f*fmaf(qx,cx,fmaf(qy,cy,qz*cz));
        d = fmaxf(d, 0.f);
        unsigned db = __float_as_uint(d);
        bool lt = db < kthb;
        unsigned lm = __ballot_sync(0xFFFFFFFFu, lt);
        if (lt) {
            int off = cnt + __popc(lm & ((1u << lane) - 1u));
            if (off < KNB) {
                gi[off] = m;
                float rx = cx-qx, ry = cy-qy, rz = cz-qz;
                a0 += rx; a1 += ry; a2 += rz;
                m00 += rx*rx; m01 += rx*ry; m02 += rx*rz;
                m11 += ry*ry; m12 += ry*rz; m22 += rz*rz;
            }
        }
        cnt += __popc(lm);
        bool eqp = (db == kthb);
        unsigned em = __ballot_sync(0xFFFFFFFFu, eqp);
        if (em) {
            if (eqp) {
                int off = eqc + __popc(em & ((1u << lane) - 1u));
                if (off < 34) eq_buf[warp][off] = m;
            }
            eqc += __popc(em);
        }
    }
    int cntc = cnt < KNB ? cnt : KNB;
    int need = KNB - cntc;
    __syncwarp();
    if (lane < need && lane < eqc && lane < 34) {
        int id = eq_buf[warp][lane];
        gi[cntc + lane] = id;
        float rx = s0[id]-qx, ry = s1[id]-qy, rz = s2[id]-qz;
        a0 += rx; a1 += ry; a2 += rz;
        m00 += rx*rx; m01 += rx*ry; m02 += rx*rz;
        m11 += ry*ry; m12 += ry*rz; m22 += rz*rz;
    }
#pragma unroll
    for (int off = 16; off > 0; off >>= 1) {
        a0  += __shfl_down_sync(~0u,a0 ,off); a1  += __shfl_down_sync(~0u,a1 ,off);
        a2  += __shfl_down_sync(~0u,a2 ,off); m00 += __shfl_down_sync(~0u,m00,off);
        m01 += __shfl_down_sync(~0u,m01,off); m02 += __shfl_down_sync(~0u,m02,off);
        m11 += __shfl_down_sync(~0u,m11,off); m12 += __shfl_down_sync(~0u,m12,off);
        m22 += __shfl_down_sync(~0u,m22,off);
    }
    if (lane == 0) {
        atomicAdd(&g_relS[0],(double)a0); atomicAdd(&g_relS[1],(double)a1);
        atomicAdd(&g_relS[2],(double)a2);
        atomicAdd(&g_relM[0],(double)m00); atomicAdd(&g_relM[1],(double)m01);
        atomicAdd(&g_relM[2],(double)m02); atomicAdd(&g_relM[3],(double)m11);
        atomicAdd(&g_relM[4],(double)m12); atomicAdd(&g_relM[5],(double)m22);
    }
}

__global__ void k_bn1fin(const float* __restrict__ Wp1,
                         const float* __restrict__ gw, const float* __restrict__ bw) {
    int c = threadIdx.x;
    double w0 = Wp1[c*3], w1 = Wp1[c*3+1], w2 = Wp1[c*3+2];
    double NT = (double)NPOINT * KNB;
    double mean = (g_relS[0]*w0 + g_relS[1]*w1 + g_relS[2]*w2) / NT;
    double E2 = (w0*w0*g_relM[0] + w1*w1*g_relM[3] + w2*w2*g_relM[5]
               + 2.0*(w0*w1*g_relM[1] + w0*w2*g_relM[2] + w1*w2*g_relM[4])) / NT;
    double var = E2 - mean*mean; if (var < 0) var = 0;
    float sc = (float)((double)gw[c] * rsqrt(var + 1e-5));
    g_scale[0][c] = sc;
    g_shift[0][c] = (float)((double)bw[c] - mean*sc);
}

// ---------------- GEMV1: pos = relu(bn(rel@Wp1)) @ Wp2
// 2 pts/thread, c-split across gridDim.y (32 channels per block), fp16 out ----------------
__global__ __launch_bounds__(128, 3) void k_mlp1(const float* __restrict__ x,
        const float* __restrict__ Wp1, const float* __restrict__ Wp2) {
    __shared__ float sA0[CH],sA1[CH],sA2[CH];
    __shared__ float sSc[CH], sSh[CH];
    __shared__ u64t sW2p[CH*16];   // [d][cpair] for this c-half, 8 KB
    int tid = threadIdx.x;
    int c0 = blockIdx.y * 32;
    for (int i = tid; i < CH; i += 128) {
        sA0[i]=Wp1[i*3]; sA1[i]=Wp1[i*3+1]; sA2[i]=Wp1[i*3+2];
        sSc[i]=g_scale[0][i]; sSh[i]=g_shift[0][i];
    }
    for (int i = tid; i < CH*16; i += 128) {
        int d = i >> 4, cp = i & 15;
        sW2p[i] = pack2(Wp2[(c0+2*cp)*CH + d], Wp2[(c0+2*cp+1)*CH + d]);
    }
    __syncthreads();
    int warp = tid >> 5, lane = tid & 31;
    size_t pA = (size_t)blockIdx.x*8 + warp*2, pB = pA + 1;
    const float* xbA = x + (size_t)(pA >> 12)*3*NPTS;
    const float* xbB = x + (size_t)(pB >> 12)*3*NPTS;
    int nA = (int)(pA & 4095), nB = (int)(pB & 4095);
    int idA = g_idx[pA*KNB + lane], idB = g_idx[pB*KNB + lane];
    float rxA = xbA[idA]-xbA[nA], ryA = xbA[NPTS+idA]-xbA[NPTS+nA], rzA = xbA[2*NPTS+idA]-xbA[2*NPTS+nA];
    float rxB = xbB[idB]-xbB[nB], ryB = xbB[NPTS+idB]-xbB[NPTS+nB], rzB = xbB[2*NPTS+idB]-xbB[2*NPTS+nB];

    u64t aA[16], aB[16];
#pragma unroll
    for (int i = 0; i < 16; i++) { aA[i] = 0ULL; aB[i] = 0ULL; }
#pragma unroll 4
    for (int d = 0; d < CH; d++) {
        float vA = fmaf(rxA, sA0[d], fmaf(ryA, sA1[d], rzA*sA2[d]));
        float uA = fmaxf(fmaf(sSc[d], vA, sSh[d]), 0.f);
        float vB = fmaf(rxB, sA0[d], fmaf(ryB, sA1[d], rzB*sA2[d]));
        float uB = fmaxf(fmaf(sSc[d], vB, sSh[d]), 0.f);
        u64t uA2 = pack2(uA, uA), uB2 = pack2(uB, uB);
        const ulonglong2* row = (const ulonglong2*)&sW2p[d*16];
#pragma unroll
        for (int i = 0; i < 8; i++) {
            ulonglong2 w = row[i];
            aA[2*i]   = fma2(uA2, w.x, aA[2*i]);
            aA[2*i+1] = fma2(uA2, w.y, aA[2*i+1]);
            aB[2*i]   = fma2(uB2, w.x, aB[2*i]);
            aB[2*i+1] = fma2(uB2, w.y, aB[2*i+1]);
        }
    }
    __half* lpA = g_posh + pA*(CH*KNB);
    __half* lpB = g_posh + pB*(CH*KNB);
#pragma unroll
    for (int i = 0; i < 16; i++) {
        float v0, v1;
        unpack2(aA[i], v0, v1);
        lpA[(c0+2*i)*KNB + lane]   = __float2half_rn(v0);
        lpA[(c0+2*i+1)*KNB + lane] = __float2half_rn(v1);
        unpack2(aB[i], v0, v1);
        lpB[(c0+2*i)*KNB + lane]   = __float2half_rn(v0);
        lpB[(c0+2*i+1)*KNB + lane] = __float2half_rn(v1);
    }
}

// ---------------- GEMV2: lp = (q - kf + pos) @ Wa
// 2 pts/thread, c-split across gridDim.y, pos prefetch (fp16), fp16 out ----------------
__global__ __launch_bounds__(128, 3) void k_mlp2(const float* __restrict__ x,
        const float* __restrict__ Wq, const float* __restrict__ Wkv,
        const float* __restrict__ Wa) {
    __shared__ float sQ0[CH],sQ1[CH],sQ2[CH];
    __shared__ float sK0[CH],sK1[CH],sK2[CH];
    __shared__ u64t sWap[CH*16];   // 8 KB, this c-half
    int tid = threadIdx.x;
    int c0 = blockIdx.y * 32;
    for (int i = tid; i < CH; i += 128) {
        sQ0[i]=Wq [i*3]; sQ1[i]=Wq [i*3+1]; sQ2[i]=Wq [i*3+2];
        sK0[i]=Wkv[i*3]; sK1[i]=Wkv[i*3+1]; sK2[i]=Wkv[i*3+2];
    }
    for (int i = tid; i < CH*16; i += 128) {
        int d = i >> 4, cp = i & 15;
        sWap[i] = pack2(Wa[(c0+2*cp)*CH + d], Wa[(c0+2*cp+1)*CH + d]);
    }
    __syncthreads();
    int warp = tid >> 5, lane = tid & 31;
    size_t pA = (size_t)blockIdx.x*8 + warp*2, pB = pA + 1;
    const float* xbA = x + (size_t)(pA >> 12)*3*NPTS;
    const float* xbB = x + (size_t)(pB >> 12)*3*NPTS;
    int nA = (int)(pA & 4095), nB = (int)(pB & 4095);
    float qxA = xbA[nA], qyA = xbA[NPTS+nA], qzA = xbA[2*NPTS+nA];
    float qxB = xbB[nB], qyB = xbB[NPTS+nB], qzB = xbB[2*NPTS+nB];
    int idA = g_idx[pA*KNB + lane], idB = g_idx[pB*KNB + lane];
    float rxA = xbA[idA]-qxA, ryA = xbA[NPTS+idA]-qyA, rzA = xbA[2*NPTS+idA]-qzA;
    float rxB = xbB[idB]-qxB, ryB = xbB[NPTS+idB]-qyB, rzB = xbB[2*NPTS+idB]-qzB;
    const __half* poA = g_posh + pA*(CH*KNB) + lane;
    const __half* poB = g_posh + pB*(CH*KNB) + lane;

    u64t aA[16], aB[16];
#pragma unroll
    for (int i = 0; i < 16; i++) { aA[i] = 0ULL; aB[i] = 0ULL; }

    // 4-deep software prefetch of pos stream
    __half pfA[4], pfB[4];
#pragma unroll
    for (int j = 0; j < 4; j++) { pfA[j] = poA[j*KNB]; pfB[j] = poB[j*KNB]; }
    for (int chunk = 0; chunk < 16; chunk++) {
        __half nxA[4], nxB[4];
        if (chunk < 15) {
#pragma unroll
            for (int j = 0; j < 4; j++) {
                nxA[j] = poA[((chunk+1)*4 + j)*KNB];
                nxB[j] = poB[((chunk+1)*4 + j)*KNB];
            }
        }
#pragma unroll
        for (int j = 0; j < 4; j++) {
            int d = chunk*4 + j;
            float w0 = sQ0[d], w1 = sQ1[d], w2 = sQ2[d];
            float k0 = sK0[d], k1 = sK1[d], k2 = sK2[d];
            float tA = fmaf(qxA,w0,fmaf(qyA,w1,qzA*w2)) - fmaf(rxA,k0,fmaf(ryA,k1,rzA*k2)) + __half2float(pfA[j]);
            float tB = fmaf(qxB,w0,fmaf(qyB,w1,qzB*w2)) - fmaf(rxB,k0,fmaf(ryB,k1,rzB*k2)) + __half2float(pfB[j]);
            u64t tA2 = pack2(tA, tA), tB2 = pack2(tB, tB);
            const ulonglong2* row = (const ulonglong2*)&sWap[d*16];
#pragma unroll
            for (int i = 0; i < 8; i++) {
                ulonglong2 w = row[i];
                aA[2*i]   = fma2(tA2, w.x, aA[2*i]);
                aA[2*i+1] = fma2(tA2, w.y, aA[2*i+1]);
                aB[2*i]   = fma2(tB2, w.x, aB[2*i]);
                aB[2*i+1] = fma2(tB2, w.y, aB[2*i+1]);
            }
        }
#pragma unroll
        for (int j = 0; j < 4; j++) { pfA[j] = nxA[j]; pfB[j] = nxB[j]; }
    }
    __half* lpA = g_lp + pA*(CH*KNB);
    __half* lpB = g_lp + pB*(CH*KNB);
#pragma unroll
    for (int i = 0; i < 16; i++) {
        float v0, v1;
        unpack2(aA[i], v0, v1);
        lpA[(c0+2*i)*KNB + lane]   = __float2half_rn(v0);
        lpA[(c0+2*i+1)*KNB + lane] = __float2half_rn(v1);
        unpack2(aB[i], v0, v1);
        lpB[(c0+2*i)*KNB + lane]   = __float2half_rn(v0);
        lpB[(c0+2*i+1)*KNB + lane] = __float2half_rn(v1);
    }
}

// ---------------- lp (fp16) channel stats reduce -> stat0 ----------------
__global__ __launch_bounds__(256) void k_reduce_lp() {
    const __half2* src = (const __half2*)g_lp;
    __shared__ float s1[CH], s2[CH];
    if (threadIdx.x < CH) { s1[threadIdx.x] = 0.f; s2[threadIdx.x] = 0.f; }
    __syncthreads();
    int t = blockIdx.x*blockDim.x + threadIdx.x;
    int stride = gridDim.x*blockDim.x;       // 512*256 = 131072
    int c = (t >> 4) & 63;
    float a = 0.f, q = 0.f;
    int total = NPOINT*CH*KNB/2;
    for (int j = t; j < total; j += stride) {
        float2 f = __half22float2(src[j]);
        a += f.x + f.y;
        q += f.x*f.x + f.y*f.y;
    }
    atomicAdd(&s1[c], a); atomicAdd(&s2[c], q);
    __syncthreads();
    if (threadIdx.x < CH) {
        atomicAdd(&g_sum[0][threadIdx.x], (double)s1[threadIdx.x]);
        atomicAdd(&g_sq [0][threadIdx.x], (double)s2[threadIdx.x]);
    }
}

// ---------------- per-channel sum/sumsq reduce (float sources) ----------------
__global__ __launch_bounds__(256) void k_reduce(int sel, int nElem, int shift, int statIdx) {
    const float* src = sel==1 ? g_hpre : sel==2 ? g_skpre : g_opre;
    __shared__ float s1[CH], s2[CH];
    if (threadIdx.x < CH) { s1[threadIdx.x] = 0.f; s2[threadIdx.x] = 0.f; }
    __syncthreads();
    int t = blockIdx.x*blockDim.x + threadIdx.x;
    int stride = gridDim.x*blockDim.x;
    int c = (t >> shift) & 63;
    float a = 0.f, q = 0.f;
    for (int i = t; i < nElem; i += stride) { float v = src[i]; a += v; q += v*v; }
    atomicAdd(&s1[c], a); atomicAdd(&s2[c], q);
    __syncthreads();
    if (threadIdx.x < CH) {
        atomicAdd(&g_sum[statIdx][threadIdx.x], (double)s1[threadIdx.x]);
        atomicAdd(&g_sq [statIdx][threadIdx.x], (double)s2[threadIdx.x]);
    }
}

// dual reduce: first blocksPer blocks -> g_hpre/stat1, rest -> g_skpre/stat2
__global__ __launch_bounds__(256) void k_reduce_hs(int blocksPer) {
    int which = blockIdx.x >= blocksPer;
    const float* src = which ? g_skpre : g_hpre;
    int statIdx = which ? 2 : 1;
    int bid = which ? blockIdx.x - blocksPer : blockIdx.x;
    __shared__ float s1[CH], s2[CH];
    if (threadIdx.x < CH) { s1[threadIdx.x] = 0.f; s2[threadIdx.x] = 0.f; }
    __syncthreads();
    int t = bid*blockDim.x + threadIdx.x;
    int stride = blocksPer*blockDim.x;
    int c = t & 63;
    float a = 0.f, q = 0.f;
    for (int i = t; i < NPOINT*CH; i += stride) { float v = src[i]; a += v; q += v*v; }
    atomicAdd(&s1[c], a); atomicAdd(&s2[c], q);
    __syncthreads();
    if (threadIdx.x < CH) {
        atomicAdd(&g_sum[statIdx][threadIdx.x], (double)s1[threadIdx.x]);
        atomicAdd(&g_sq [statIdx][threadIdx.x], (double)s2[threadIdx.x]);
    }
}

__global__ void k_bnfin(int statIdx, int bnIdx, float cnt,
                        const float* __restrict__ gw, const float* __restrict__ bw) {
    int c = threadIdx.x;
    double mean = g_sum[statIdx][c] / (double)cnt;
    double var  = g_sq [statIdx][c] / (double)cnt - mean*mean;
    if (var < 0) var = 0;
    float sc = (float)((double)gw[c] * rsqrt(var + 1e-5));
    g_scale[bnIdx][c] = sc;
    g_shift[bnIdx][c] = (float)((double)bw[c] - mean*sc);
}

__global__ void k_bnfin2(const float* __restrict__ gc, const float* __restrict__ bc,
                         const float* __restrict__ gs, const float* __restrict__ bs) {
    int c = threadIdx.x & 63;
    int which = threadIdx.x >> 6;
    int statIdx = which ? 2 : 1;
    int bnIdx   = which ? 3 : 2;
    const float* gw = which ? gs : gc;
    const float* bw = which ? bs : bc;
    double mean = g_sum[statIdx][c] / (double)NPOINT;
    double var  = g_sq [statIdx][c] / (double)NPOINT - mean*mean;
    if (var < 0) var = 0;
    float sc = (float)((double)gw[c] * rsqrt(var + 1e-5));
    g_scale[bnIdx][c] = sc;
    g_shift[bnIdx][c] = (float)((double)bw[c] - mean*sc);
}

// ---------------- attention + aggregation + h/sk pre ----------------
__global__ __launch_bounds__(128) void k_attn(const float* __restrict__ x,
        const float* __restrict__ Wkv, const float* __restrict__ Wc1,
        const float* __restrict__ Wsk) {
    __shared__ float sV0[CH], sV1[CH], sV2[CH];
    __shared__ float sC1T[CH*CH];   // [d][c]
    __shared__ float sSkT[6*CH];    // [j][c]
    __shared__ float rels[4][3][KNB];
    __shared__ float aggs[4][CH];
    int tid = threadIdx.x;
    for (int i = tid; i < CH; i += 128) {
        sV0[i]=Wkv[(CH+i)*3]; sV1[i]=Wkv[(CH+i)*3+1]; sV2[i]=Wkv[(CH+i)*3+2];
    }
    for (int i = tid; i < CH*CH; i += 128) {
        int d = i >> 6, c = i & 63;
        sC1T[i] = Wc1[c*CH + d];
    }
    for (int i = tid; i < 6*CH; i += 128) {
        int j = i >> 6, c = i & 63;
        sSkT[i] = Wsk[c*6 + j];
    }
    __syncthreads();
    int warp = tid >> 5, lane = tid & 31;
    size_t p = (size_t)blockIdx.x*4 + warp;
    int b = (int)(p >> 12), n = (int)(p & 4095);
    const float* xb = x + (size_t)b*3*NPTS;
    float qx = xb[n], qy = xb[NPTS+n], qz = xb[2*NPTS+n];
    int id = g_idx[p*KNB + lane];
    float cx = xb[id], cy = xb[NPTS+id], cz = xb[2*NPTS+id];
    rels[warp][0][lane] = cx-qx; rels[warp][1][lane] = cy-qy; rels[warp][2][lane] = cz-qz;
    float mx = cx, my = cy, mz = cz;
#pragma unroll
    for (int off = 16; off > 0; off >>= 1) {
        mx = fmaxf(mx, __shfl_xor_sync(~0u, mx, off));
        my = fmaxf(my, __shfl_xor_sync(~0u, my, off));
        mz = fmaxf(mz, __shfl_xor_sync(~0u, mz, off));
    }
    __syncwarp();
#pragma unroll
    for (int half = 0; half < 2; half++) {
        int c = lane + 32*half;
        float lg[KNB], pv[KNB];
        const __half2* lp2 = (const __half2*)(g_lp   + p*(CH*KNB) + (size_t)c*KNB);
        const __half2* po2 = (const __half2*)(g_posh + p*(CH*KNB) + (size_t)c*KNB);
#pragma unroll
        for (int i = 0; i < KNB/2; i++) {
            float2 f = __half22float2(lp2[i]);
            lg[2*i] = f.x; lg[2*i+1] = f.y;
        }
#pragma unroll
        for (int i = 0; i < KNB/2; i++) {
            float2 w = __half22float2(po2[i]);
            pv[2*i] = w.x; pv[2*i+1] = w.y;
        }
        float scl = g_scale[1][c], shf = g_shift[1][c];
        float m = 0.f;
#pragma unroll
        for (int j = 0; j < KNB; j++) { lg[j] = fmaxf(scl*lg[j]+shf, 0.f); m = fmaxf(m, lg[j]); }
        float s = 0.f;
#pragma unroll
        for (int j = 0; j < KNB; j++) { lg[j] = __expf(lg[j]-m); s += lg[j]; }
        float r = 1.f/s;
        float w0 = sV0[c], w1 = sV1[c], w2 = sV2[c];
        float a = 0.f;
#pragma unroll
        for (int j = 0; j < KNB; j++) {
            float vf = rels[warp][0][j]*w0 + rels[warp][1][j]*w1 + rels[warp][2][j]*w2;
            a += lg[j]*(vf + pv[j]);
        }
        aggs[warp][c] = a*r;
    }
    __syncwarp();
#pragma unroll
    for (int half = 0; half < 2; half++) {
        int c = lane + 32*half;
        float acc = 0.f;
#pragma unroll 8
        for (int d = 0; d < CH; d++) acc += aggs[warp][d]*sC1T[d*CH + c];
        g_hpre[p*CH + c] = acc;
        g_skpre[p*CH + c] = qx*sSkT[0*CH+c] + qy*sSkT[1*CH+c] + qz*sSkT[2*CH+c]
                          + mx*sSkT[3*CH+c] + my*sSkT[4*CH+c] + mz*sSkT[5*CH+c];
    }
}

// ---------------- gate GEMV 128->64 ----------------
__global__ __launch_bounds__(128) void k_out1(const float* __restrict__ Wga) {
    __shared__ float sWT[128*CH];
    __shared__ float hs[4][128];
    int tid = threadIdx.x;
    for (int idx = tid; idx < CH*128; idx += 128) {
        int i = idx >> 6, c = idx & 63;
        sWT[idx] = Wga[c*128 + i];
    }
    __syncthreads();
    int warp = tid >> 5, lane = tid & 31;
    size_t p = (size_t)blockIdx.x*4 + warp;
#pragma unroll
    for (int half = 0; half < 2; half++) {
        int c = lane + 32*half;
        hs[warp][c]     = fmaxf(g_scale[2][c]*g_hpre [p*CH+c] + g_shift[2][c], 0.f);
        hs[warp][64+c]  = fmaxf(g_scale[3][c]*g_skpre[p*CH+c] + g_shift[3][c], 0.f);
    }
    __syncwarp();
#pragma unroll
    for (int half = 0; half < 2; half++) {
        int c = lane + 32*half;
        float acc = 0.f;
#pragma unroll 8
        for (int i = 0; i < 128; i++) acc += hs[warp][i] * sWT[i*CH + c];
        g_opre[p*CH + c] = acc;
    }
}

// ---------------- final BN + transpose ----------------
__global__ __launch_bounds__(256) void k_out2(float* __restrict__ out) {
    int total = NPOINT*CH;
    for (int o = blockIdx.x*blockDim.x + threadIdx.x; o < total; o += gridDim.x*blockDim.x) {
        int n  = o & 4095;
        int bc = o >> 12;
        int c  = bc & 63;
        int b  = bc >> 6;
        float v = g_opre[(((size_t)b<<12) + n)*CH + c];
        out[o] = fmaxf(g_scale[4][c]*v + g_shift[4][c], 0.f);
    }
}

extern "C" void kernel_launch(void* const* d_in, const int* in_sizes, int n_in,
                              void* d_out, int out_size) {
    const float* x   = (const float*)d_in[0];
    const float* Wq  = (const float*)d_in[1];
    const float* Wkv = (const float*)d_in[2];
    const float* Wp1 = (const float*)d_in[3];
    const float* Wp2 = (const float*)d_in[4];
    const float* Wa  = (const float*)d_in[5];
    const float* Wc1 = (const float*)d_in[6];
    const float* Wsk = (const float*)d_in[7];
    const float* Wga = (const float*)d_in[8];
    const float* g_p = (const float*)d_in[9],  *b_p = (const float*)d_in[10];
    const float* g_a = (const float*)d_in[11], *b_a = (const float*)d_in[12];
    const float* g_c = (const float*)d_in[13], *b_c = (const float*)d_in[14];
    const float* g_sk= (const float*)d_in[15], *b_sk= (const float*)d_in[16];
    const float* g_ga= (const float*)d_in[17], *b_ga= (const float*)d_in[18];
    float* out = (float*)d_out;

    k_zero<<<1,256>>>();
    k_knn<<<dim3(NPTS/4, NBATCH), 128>>>(x);
    k_bn1fin<<<1,64>>>(Wp1, g_p, b_p);
    k_mlp1<<<dim3(NPOINT/8, 2), 128>>>(x, Wp1, Wp2);
    k_mlp2<<<dim3(NPOINT/8, 2), 128>>>(x, Wq, Wkv, Wa);
    k_reduce_lp<<<512,256>>>();
    k_bnfin<<<1,64>>>(0, 1, (float)(NPOINT*KNB), g_a, b_a);
    k_attn<<<NPOINT/4, 128>>>(x, Wkv, Wc1, Wsk);
    k_reduce_hs<<<512,256>>>(256);
    k_bnfin2<<<1,128>>>(g_c, b_c, g_sk, b_sk);
    k_out1<<<NPOINT/4, 128>>>(Wga);
    k_reduce<<<256,256>>>(3, NPOINT*CH, 0, 3);
    k_bnfin<<<1,64>>>(3, 4, (float)NPOINT, g_ga, b_ga);
    k_out2<<<512,256>>>(out);
}